// round 1
// baseline (speedup 1.0000x reference)
#include <cuda_runtime.h>
#include <math.h>

#define B_    128
#define T_    256
#define IN_   256
#define HID_  512
#define NG_   1536   // 3*HID
#define OUT_  64

// ---------------- scratch (static __device__, no allocation) ----------------
__device__ float g_xg[(size_t)B_ * T_ * NG_];    // 201 MB: xg for current layer
__device__ float g_h0[(size_t)B_ * T_ * HID_];   // 64 MB: layer-0 hidden sequence
__device__ float g_h1[(size_t)B_ * T_ * HID_];   // 64 MB: layer-1 hidden sequence
__device__ unsigned g_ctr[2];                    // grid-barrier counters (memset each launch)

// ============================================================================
// GEMM: out[M,N] = X[M,K] @ W[N,K]^T + bias[N]      (both operands K-major)
// Tiles: 128x64x16, 256 threads, 8x4 per-thread micro-tile.
// ============================================================================
#define GBM 128
#define GBN 64
#define GBK 16

__global__ __launch_bounds__(256)
void gemm_bias(const float* __restrict__ X, const float* __restrict__ W,
               const float* __restrict__ bias, float* __restrict__ out,
               int M, int N, int K)
{
    __shared__ float Xs[GBK][GBM + 4];   // [k][m], pad 4 to break STS conflicts
    __shared__ float Ws[GBK][GBN + 4];   // [k][n]

    const int tid = threadIdx.x;
    const int tx  = tid & 15;            // 0..15 -> 4 cols each
    const int ty  = tid >> 4;            // 0..15 -> 8 rows each
    const int m0  = blockIdx.y * GBM;
    const int n0  = blockIdx.x * GBN;

    float acc[8][4];
#pragma unroll
    for (int i = 0; i < 8; i++)
#pragma unroll
        for (int j = 0; j < 4; j++) acc[i][j] = 0.f;

    for (int k0 = 0; k0 < K; k0 += GBK) {
        // X tile: 128 rows x 16 k = 512 float4, 2 per thread
#pragma unroll
        for (int l = 0; l < 2; l++) {
            int idx = l * 256 + tid;
            int r = idx >> 2;            // 0..127
            int c = idx & 3;             // float4 within the 16-wide k slab
            float4 v = *(const float4*)(X + (size_t)(m0 + r) * K + k0 + c * 4);
            Xs[c * 4 + 0][r] = v.x; Xs[c * 4 + 1][r] = v.y;
            Xs[c * 4 + 2][r] = v.z; Xs[c * 4 + 3][r] = v.w;
        }
        // W tile: 64 rows x 16 k = 256 float4, 1 per thread
        {
            int r = tid >> 2;
            int c = tid & 3;
            float4 v = *(const float4*)(W + (size_t)(n0 + r) * K + k0 + c * 4);
            Ws[c * 4 + 0][r] = v.x; Ws[c * 4 + 1][r] = v.y;
            Ws[c * 4 + 2][r] = v.z; Ws[c * 4 + 3][r] = v.w;
        }
        __syncthreads();

#pragma unroll
        for (int kk = 0; kk < GBK; kk++) {
            float4 a0 = *(const float4*)&Xs[kk][ty * 8];
            float4 a1 = *(const float4*)&Xs[kk][ty * 8 + 4];
            float4 b0 = *(const float4*)&Ws[kk][tx * 4];
            float a[8] = {a0.x, a0.y, a0.z, a0.w, a1.x, a1.y, a1.z, a1.w};
            float bb[4] = {b0.x, b0.y, b0.z, b0.w};
#pragma unroll
            for (int i = 0; i < 8; i++)
#pragma unroll
                for (int j = 0; j < 4; j++)
                    acc[i][j] += a[i] * bb[j];
        }
        __syncthreads();
    }

    float4 bv = *(const float4*)(bias + n0 + tx * 4);
#pragma unroll
    for (int i = 0; i < 8; i++) {
        int m = m0 + ty * 8 + i;
        float4 o;
        o.x = acc[i][0] + bv.x; o.y = acc[i][1] + bv.y;
        o.z = acc[i][2] + bv.z; o.w = acc[i][3] + bv.w;
        *(float4*)(out + (size_t)m * N + n0 + tx * 4) = o;
    }
}

// ============================================================================
// Persistent GRU recurrence.
// Grid: 64 unit-tiles (8 units each) x 2 batch-tiles (64 rows each) = 128 CTAs,
// all resident (1 CTA/SM by smem). Per step: each CTA recomputes hg for its
// (batch-tile x 8-unit) patch from the h tile staged in smem; a grid-wide
// barrier (monotonic counter) separates steps. W_hh rows live in smem for the
// whole kernel.
// ============================================================================
#define RBT 64               // batch rows per CTA
#define RUT 8                // hidden units per CTA
#define HP  516              // padded row stride (bank-conflict free)
#define REC_SMEM_BYTES ((RBT * HP + 3 * RUT * HP) * 4)

__global__ __launch_bounds__(256)
void gru_rec(const float* __restrict__ xg,   // [B*T, 1536] (b_ih included)
             const float* __restrict__ Whh,  // [1536, 512]
             const float* __restrict__ bhh,  // [1536]
             float* __restrict__ hseq,       // [B, T, 512]
             unsigned* __restrict__ ctr)
{
    extern __shared__ float sm[];
    float* h_s = sm;                 // [RBT][HP] : previous h tile (full 512 cols)
    float* W_s = sm + RBT * HP;      // [24][HP]  : W_hh rows for this CTA's 8 units x 3 gates
    __shared__ float bh_s[24];

    const int tid = threadIdx.x;
    const int u0  = blockIdx.x * RUT;
    const int b0  = blockIdx.y * RBT;
    const unsigned nCTA = gridDim.x * gridDim.y;

    // preload W_hh rows (24 x 512) and b_hh — constant across all steps
    for (int i = tid; i < 24 * (HID_ / 4); i += 256) {
        int r  = i >> 7;             // 0..23  (g*8 + u)
        int c4 = i & 127;
        int g = r >> 3, u = r & 7;
        float4 v = *(const float4*)(Whh + (size_t)(g * HID_ + u0 + u) * HID_ + c4 * 4);
        *(float4*)&W_s[r * HP + c4 * 4] = v;
    }
    if (tid < 24) {
        int g = tid >> 3, u = tid & 7;
        bh_s[tid] = bhh[g * HID_ + u0 + u];
    }

    const int ug    = tid & 3;       // 4 unit-groups of 2 units
    const int b     = tid >> 2;      // 0..63 batch row within tile
    const int bglob = b0 + b;
    const int ul0   = ug * 2;        // local unit 0..7 (pair base)
    const float* hrow = h_s + b * HP;

    const float* w00 = W_s + (0 * 8 + ul0) * HP;
    const float* w01 = w00 + HP;
    const float* w10 = W_s + (1 * 8 + ul0) * HP;
    const float* w11 = w10 + HP;
    const float* w20 = W_s + (2 * 8 + ul0) * HP;
    const float* w21 = w20 + HP;

    for (int t = 0; t < T_; t++) {
        // stage previous h tile [64 x 512] into smem
        if (t == 0) {
            for (int i = tid; i < RBT * (HID_ / 4); i += 256)
                *(float4*)&h_s[(i >> 7) * HP + (i & 127) * 4] = make_float4(0.f, 0.f, 0.f, 0.f);
        } else {
            for (int i = tid; i < RBT * (HID_ / 4); i += 256) {
                int r = i >> 7, c4 = i & 127;
                float4 v = *(const float4*)(hseq + ((size_t)(b0 + r) * T_ + (t - 1)) * HID_ + c4 * 4);
                *(float4*)&h_s[r * HP + c4 * 4] = v;
            }
        }
        __syncthreads();

        float acc00 = bh_s[ul0],      acc01 = bh_s[ul0 + 1];
        float acc10 = bh_s[8 + ul0],  acc11 = bh_s[8 + ul0 + 1];
        float acc20 = bh_s[16 + ul0], acc21 = bh_s[16 + ul0 + 1];

#pragma unroll 4
        for (int k = 0; k < HID_; k += 4) {
            float4 hv = *(const float4*)(hrow + k);
            float4 v;
            v = *(const float4*)(w00 + k); acc00 += hv.x*v.x + hv.y*v.y + hv.z*v.z + hv.w*v.w;
            v = *(const float4*)(w01 + k); acc01 += hv.x*v.x + hv.y*v.y + hv.z*v.z + hv.w*v.w;
            v = *(const float4*)(w10 + k); acc10 += hv.x*v.x + hv.y*v.y + hv.z*v.z + hv.w*v.w;
            v = *(const float4*)(w11 + k); acc11 += hv.x*v.x + hv.y*v.y + hv.z*v.z + hv.w*v.w;
            v = *(const float4*)(w20 + k); acc20 += hv.x*v.x + hv.y*v.y + hv.z*v.z + hv.w*v.w;
            v = *(const float4*)(w21 + k); acc21 += hv.x*v.x + hv.y*v.y + hv.z*v.z + hv.w*v.w;
        }

        const size_t xb = ((size_t)bglob * T_ + t) * NG_ + u0 + ul0;
        const size_t hb = ((size_t)bglob * T_ + t) * HID_ + u0 + ul0;
#pragma unroll
        for (int j = 0; j < 2; j++) {
            float hr = j ? acc01 : acc00;
            float hz = j ? acc11 : acc10;
            float hn = j ? acc21 : acc20;
            float xr = xg[xb + j];
            float xz = xg[xb + 512 + j];
            float xn = xg[xb + 1024 + j];
            float r  = 1.f / (1.f + __expf(-(xr + hr)));
            float z  = 1.f / (1.f + __expf(-(xz + hz)));
            float n  = tanhf(xn + r * hn);
            float hp = hrow[u0 + ul0 + j];
            hseq[hb + j] = (1.f - z) * n + z * hp;
        }
        __syncthreads();   // protect h_s before next-step refill

        if (t < T_ - 1) {
            // grid-wide barrier: monotonic counter, all 128 CTAs resident
            if (tid == 0) {
                __threadfence();                 // release this block's h writes
                atomicAdd(ctr, 1u);
                unsigned target = (unsigned)(t + 1) * nCTA;
                volatile unsigned* vc = ctr;
                while (*vc < target) { }
                __threadfence();                 // acquire other blocks' h writes
            }
            __syncthreads();
        }
    }
}

// ============================================================================
// Head: y[b,o] = h_last[b,:] . W_out[o,:] + b_out[o]
// ============================================================================
__global__ __launch_bounds__(64)
void out_proj(const float* __restrict__ hseq, const float* __restrict__ Wout,
              const float* __restrict__ bout, float* __restrict__ y)
{
    __shared__ float hs[HID_];
    const int b = blockIdx.x;
    const float* h = hseq + ((size_t)b * T_ + (T_ - 1)) * HID_;
    for (int i = threadIdx.x; i < HID_; i += 64) hs[i] = h[i];
    __syncthreads();

    const int o = threadIdx.x;
    float acc = bout[o];
    const float* w = Wout + (size_t)o * HID_;
#pragma unroll 4
    for (int k = 0; k < HID_; k += 4) {
        float4 wv = *(const float4*)(w + k);
        acc += hs[k] * wv.x + hs[k + 1] * wv.y + hs[k + 2] * wv.z + hs[k + 3] * wv.w;
    }
    y[b * OUT_ + o] = acc;
}

// ============================================================================
extern "C" void kernel_launch(void* const* d_in, const int* in_sizes, int n_in,
                              void* d_out, int out_size)
{
    (void)in_sizes; (void)n_in; (void)out_size;
    const float* x     = (const float*)d_in[0];
    const float* W_ih0 = (const float*)d_in[1];
    const float* W_hh0 = (const float*)d_in[2];
    const float* b_ih0 = (const float*)d_in[3];
    const float* b_hh0 = (const float*)d_in[4];
    const float* W_ih1 = (const float*)d_in[5];
    const float* W_hh1 = (const float*)d_in[6];
    const float* b_ih1 = (const float*)d_in[7];
    const float* b_hh1 = (const float*)d_in[8];
    const float* W_out = (const float*)d_in[9];
    const float* b_out = (const float*)d_in[10];
    float* y = (float*)d_out;

    float *xg, *h0, *h1;
    unsigned* ctr;
    cudaGetSymbolAddress((void**)&xg, g_xg);
    cudaGetSymbolAddress((void**)&h0, g_h0);
    cudaGetSymbolAddress((void**)&h1, g_h1);
    cudaGetSymbolAddress((void**)&ctr, g_ctr);

    cudaFuncSetAttribute(gru_rec, cudaFuncAttributeMaxDynamicSharedMemorySize,
                         REC_SMEM_BYTES);

    // reset grid-barrier counters (graph-replay safe: captured memset node)
    cudaMemsetAsync(ctr, 0, 2 * sizeof(unsigned));

    const dim3 ggrid(NG_ / GBN, (B_ * T_) / GBM);   // 24 x 256

    // layer 0
    gemm_bias<<<ggrid, 256>>>(x, W_ih0, b_ih0, xg, B_ * T_, NG_, IN_);
    gru_rec<<<dim3(HID_ / RUT, B_ / RBT), 256, REC_SMEM_BYTES>>>(xg, W_hh0, b_hh0, h0, ctr);

    // layer 1
    gemm_bias<<<ggrid, 256>>>(h0, W_ih1, b_ih1, xg, B_ * T_, NG_, HID_);
    gru_rec<<<dim3(HID_ / RUT, B_ / RBT), 256, REC_SMEM_BYTES>>>(xg, W_hh1, b_hh1, h1, ctr + 1);

    // head
    out_proj<<<B_, 64>>>(h1, W_out, b_out, y);
}

// round 2
// speedup vs baseline: 1.5832x; 1.5832x over previous
#include <cuda_runtime.h>
#include <math.h>

#define B_    128
#define T_    256
#define IN_   256
#define HID_  512
#define NG_   1536   // 3*HID
#define OUT_  64

// ---------------- scratch (static __device__, no allocation) ----------------
__device__ float g_xg[(size_t)B_ * T_ * NG_];    // xg for current layer
__device__ float g_h0[(size_t)B_ * T_ * HID_];   // layer-0 hidden sequence
__device__ float g_h1[(size_t)B_ * T_ * HID_];   // layer-1 hidden sequence
__device__ unsigned g_ctr[2];                    // grid-barrier counters

// ============================================================================
// GEMM: out[M,N] = X[M,K] @ W[N,K]^T + bias[N]   (both K-major)
// 128x128x8 tile, 256 threads, 8x8 micro-tile, register prefetch, 2 CTAs/SM.
// ============================================================================
#define BM 128
#define BN 128
#define BK 8

__global__ __launch_bounds__(256, 2)
void gemm_bias(const float* __restrict__ X, const float* __restrict__ W,
               const float* __restrict__ bias, float* __restrict__ out,
               int M, int N, int K)
{
    __shared__ float As[BK][BM];   // [k][m]
    __shared__ float Bs[BK][BN];   // [k][n]

    const int tid = threadIdx.x;
    const int tx  = tid & 15;          // 0..15 -> 8 cols
    const int ty  = tid >> 4;          // 0..15 -> 8 rows
    const int m0  = blockIdx.y * BM;
    const int n0  = blockIdx.x * BN;

    // global-load assignment: 2 threads per row, one float4 each
    const int lr = tid >> 1;           // 0..127 row within tile
    const int lc = (tid & 1) * 4;      // k offset 0 or 4

    const float* Xp = X + (size_t)(m0 + lr) * K + lc;
    const float* Wp = W + (size_t)(n0 + lr) * K + lc;

    float acc[8][8];
#pragma unroll
    for (int i = 0; i < 8; i++)
#pragma unroll
        for (int j = 0; j < 8; j++) acc[i][j] = 0.f;

    float4 pa = *(const float4*)Xp;
    float4 pb = *(const float4*)Wp;

    for (int k0 = 0; k0 < K; k0 += BK) {
        // store prefetched slab (transposed)
        As[lc + 0][lr] = pa.x; As[lc + 1][lr] = pa.y;
        As[lc + 2][lr] = pa.z; As[lc + 3][lr] = pa.w;
        Bs[lc + 0][lr] = pb.x; Bs[lc + 1][lr] = pb.y;
        Bs[lc + 2][lr] = pb.z; Bs[lc + 3][lr] = pb.w;
        __syncthreads();

        if (k0 + BK < K) {
            pa = *(const float4*)(Xp + k0 + BK);
            pb = *(const float4*)(Wp + k0 + BK);
        }

#pragma unroll
        for (int kk = 0; kk < BK; kk++) {
            float4 a0 = *(const float4*)&As[kk][ty * 8];
            float4 a1 = *(const float4*)&As[kk][ty * 8 + 4];
            float4 b0 = *(const float4*)&Bs[kk][tx * 8];
            float4 b1 = *(const float4*)&Bs[kk][tx * 8 + 4];
            float a[8] = {a0.x, a0.y, a0.z, a0.w, a1.x, a1.y, a1.z, a1.w};
            float b[8] = {b0.x, b0.y, b0.z, b0.w, b1.x, b1.y, b1.z, b1.w};
#pragma unroll
            for (int i = 0; i < 8; i++)
#pragma unroll
                for (int j = 0; j < 8; j++)
                    acc[i][j] += a[i] * b[j];
        }
        __syncthreads();
    }

    float4 bv0 = *(const float4*)(bias + n0 + tx * 8);
    float4 bv1 = *(const float4*)(bias + n0 + tx * 8 + 4);
#pragma unroll
    for (int i = 0; i < 8; i++) {
        int m = m0 + ty * 8 + i;
        float4 o0, o1;
        o0.x = acc[i][0] + bv0.x; o0.y = acc[i][1] + bv0.y;
        o0.z = acc[i][2] + bv0.z; o0.w = acc[i][3] + bv0.w;
        o1.x = acc[i][4] + bv1.x; o1.y = acc[i][5] + bv1.y;
        o1.z = acc[i][6] + bv1.z; o1.w = acc[i][7] + bv1.w;
        *(float4*)(out + (size_t)m * N + n0 + tx * 8)     = o0;
        *(float4*)(out + (size_t)m * N + n0 + tx * 8 + 4) = o1;
    }
}

// ============================================================================
// Persistent GRU recurrence.
// 128 CTAs (64 unit-tiles x 2 batch-tiles), all resident, grid barrier per step.
// CTA = 64 batch rows x 8 units. 256 threads = 2 k-split groups x 128.
// Thread micro-tile: 4 batch rows (stride 16) x 3 gates of one unit ->
// 12 accumulators, 48 FFMA per 7 LDS.128.
// ============================================================================
#define RBT 64               // batch rows per CTA
#define RUT 8                // hidden units per CTA
#define HP  516              // padded row stride (floats)
#define KSPLIT 256           // k depth per group
#define REC_SMEM_FLOATS (RBT * HP + 3 * RUT * HP + 12 * 128)
#define REC_SMEM_BYTES  (REC_SMEM_FLOATS * 4)

__global__ __launch_bounds__(256)
void gru_rec(const float* __restrict__ xg,   // [B*T, 1536]
             const float* __restrict__ Whh,  // [1536, 512]
             const float* __restrict__ bhh,  // [1536]
             float* __restrict__ hseq,       // [B, T, 512]
             unsigned* __restrict__ ctr)
{
    extern __shared__ float sm[];
    float* h_s = sm;                        // [RBT][HP]
    float* W_s = sm + RBT * HP;             // [24][HP], row = gate*8 + unit
    float* red = sm + RBT * HP + 24 * HP;   // [128][12] partial sums
    __shared__ float bh_s[24];

    const int tid = threadIdx.x;
    const int u0  = blockIdx.x * RUT;
    const int b0  = blockIdx.y * RBT;
    const unsigned nCTA = gridDim.x * gridDim.y;

    // preload W_hh rows (24 x 512) and b_hh
    for (int i = tid; i < 24 * (HID_ / 4); i += 256) {
        int r  = i >> 7;             // 0..23
        int c4 = i & 127;
        int g = r >> 3, u = r & 7;
        float4 v = *(const float4*)(Whh + (size_t)(g * HID_ + u0 + u) * HID_ + c4 * 4);
        *(float4*)&W_s[r * HP + c4 * 4] = v;
    }
    if (tid < 24) {
        int g = tid >> 3, u = tid & 7;
        bh_s[tid] = bhh[g * HID_ + u0 + u];
    }

    const int ks = tid >> 7;         // k-split group 0/1
    const int r  = tid & 127;
    const int ug = r & 7;            // unit 0..7
    const int bg = r >> 3;           // batch group 0..15 -> rows bg+16i
    const int kb = ks * KSPLIT;

    const float* wr = W_s + (0 * 8 + ug) * HP + kb;
    const float* wz = W_s + (1 * 8 + ug) * HP + kb;
    const float* wn = W_s + (2 * 8 + ug) * HP + kb;
    const float* h0p = h_s + (bg +  0) * HP + kb;
    const float* h1p = h_s + (bg + 16) * HP + kb;
    const float* h2p = h_s + (bg + 32) * HP + kb;
    const float* h3p = h_s + (bg + 48) * HP + kb;

    for (int t = 0; t < T_; t++) {
        // ---- stage previous h tile [64 x 512] into smem ----
        if (t == 0) {
            for (int i = tid; i < RBT * (HID_ / 4); i += 256)
                *(float4*)&h_s[(i >> 7) * HP + (i & 127) * 4] =
                    make_float4(0.f, 0.f, 0.f, 0.f);
        } else {
            for (int i = tid; i < RBT * (HID_ / 4); i += 256) {
                int rr = i >> 7, c4 = i & 127;
                float4 v = *(const float4*)(hseq +
                    ((size_t)(b0 + rr) * T_ + (t - 1)) * HID_ + c4 * 4);
                *(float4*)&h_s[rr * HP + c4 * 4] = v;
            }
        }
        __syncthreads();

        // ---- prefetch xg[t] for this thread's 4 (b,unit) outputs (ks0 only) ----
        float xr[4], xz[4], xn[4];
        if (ks == 0) {
#pragma unroll
            for (int i = 0; i < 4; i++) {
                size_t xb = ((size_t)(b0 + bg + 16 * i) * T_ + t) * NG_ + u0 + ug;
                xr[i] = __ldg(xg + xb);
                xz[i] = __ldg(xg + xb + 512);
                xn[i] = __ldg(xg + xb + 1024);
            }
        }

        // ---- accumulate hg over this group's k half ----
        float ar0, ar1, ar2, ar3, az0, az1, az2, az3, an0, an1, an2, an3;
        if (ks == 0) {
            ar0 = ar1 = ar2 = ar3 = bh_s[ug];
            az0 = az1 = az2 = az3 = bh_s[8 + ug];
            an0 = an1 = an2 = an3 = bh_s[16 + ug];
        } else {
            ar0 = ar1 = ar2 = ar3 = 0.f;
            az0 = az1 = az2 = az3 = 0.f;
            an0 = an1 = an2 = an3 = 0.f;
        }

#pragma unroll 2
        for (int k = 0; k < KSPLIT; k += 4) {
            float4 w0 = *(const float4*)(wr + k);
            float4 w1 = *(const float4*)(wz + k);
            float4 w2 = *(const float4*)(wn + k);
            float4 hA = *(const float4*)(h0p + k);
            float4 hB = *(const float4*)(h1p + k);
            float4 hC = *(const float4*)(h2p + k);
            float4 hD = *(const float4*)(h3p + k);

            ar0 += hA.x*w0.x + hA.y*w0.y + hA.z*w0.z + hA.w*w0.w;
            ar1 += hB.x*w0.x + hB.y*w0.y + hB.z*w0.z + hB.w*w0.w;
            ar2 += hC.x*w0.x + hC.y*w0.y + hC.z*w0.z + hC.w*w0.w;
            ar3 += hD.x*w0.x + hD.y*w0.y + hD.z*w0.z + hD.w*w0.w;
            az0 += hA.x*w1.x + hA.y*w1.y + hA.z*w1.z + hA.w*w1.w;
            az1 += hB.x*w1.x + hB.y*w1.y + hB.z*w1.z + hB.w*w1.w;
            az2 += hC.x*w1.x + hC.y*w1.y + hC.z*w1.z + hC.w*w1.w;
            az3 += hD.x*w1.x + hD.y*w1.y + hD.z*w1.z + hD.w*w1.w;
            an0 += hA.x*w2.x + hA.y*w2.y + hA.z*w2.z + hA.w*w2.w;
            an1 += hB.x*w2.x + hB.y*w2.y + hB.z*w2.z + hB.w*w2.w;
            an2 += hC.x*w2.x + hC.y*w2.y + hC.z*w2.z + hC.w*w2.w;
            an3 += hD.x*w2.x + hD.y*w2.y + hD.z*w2.z + hD.w*w2.w;
        }

        // ---- cross-group reduction ----
        if (ks == 1) {
            float* rp = red + r * 12;
            rp[0] = ar0; rp[1]  = ar1; rp[2]  = ar2; rp[3]  = ar3;
            rp[4] = az0; rp[5]  = az1; rp[6]  = az2; rp[7]  = az3;
            rp[8] = an0; rp[9]  = an1; rp[10] = an2; rp[11] = an3;
        }
        __syncthreads();

        if (ks == 0) {
            const float* rp = red + r * 12;
            ar0 += rp[0]; ar1 += rp[1];  ar2 += rp[2];  ar3 += rp[3];
            az0 += rp[4]; az1 += rp[5];  az2 += rp[6];  az3 += rp[7];
            an0 += rp[8]; an1 += rp[9];  an2 += rp[10]; an3 += rp[11];

            float hr[4] = {ar0, ar1, ar2, ar3};
            float hz[4] = {az0, az1, az2, az3};
            float hn[4] = {an0, an1, an2, an3};
#pragma unroll
            for (int i = 0; i < 4; i++) {
                int b = b0 + bg + 16 * i;
                float rr = 1.f / (1.f + __expf(-(xr[i] + hr[i])));
                float zz = 1.f / (1.f + __expf(-(xz[i] + hz[i])));
                float nn = tanhf(xn[i] + rr * hn[i]);
                float hp = h_s[(bg + 16 * i) * HP + u0 + ug];
                hseq[((size_t)b * T_ + t) * HID_ + u0 + ug] =
                    (1.f - zz) * nn + zz * hp;
            }
        }
        __syncthreads();   // h_s / red reads done

        if (t < T_ - 1) {
            if (tid == 0) {
                __threadfence();
                atomicAdd(ctr, 1u);
                unsigned target = (unsigned)(t + 1) * nCTA;
                volatile unsigned* vc = ctr;
                while (*vc < target) { }
                __threadfence();
            }
            __syncthreads();
        }
    }
}

// ============================================================================
// Head: y[b,o] = h_last[b,:] . W_out[o,:] + b_out[o]
// ============================================================================
__global__ __launch_bounds__(64)
void out_proj(const float* __restrict__ hseq, const float* __restrict__ Wout,
              const float* __restrict__ bout, float* __restrict__ y)
{
    __shared__ float hs[HID_];
    const int b = blockIdx.x;
    const float* h = hseq + ((size_t)b * T_ + (T_ - 1)) * HID_;
    for (int i = threadIdx.x; i < HID_; i += 64) hs[i] = h[i];
    __syncthreads();

    const int o = threadIdx.x;
    float acc = bout[o];
    const float* w = Wout + (size_t)o * HID_;
#pragma unroll 4
    for (int k = 0; k < HID_; k += 4) {
        float4 wv = *(const float4*)(w + k);
        acc += hs[k] * wv.x + hs[k + 1] * wv.y + hs[k + 2] * wv.z + hs[k + 3] * wv.w;
    }
    y[b * OUT_ + o] = acc;
}

// ============================================================================
extern "C" void kernel_launch(void* const* d_in, const int* in_sizes, int n_in,
                              void* d_out, int out_size)
{
    (void)in_sizes; (void)n_in; (void)out_size;
    const float* x     = (const float*)d_in[0];
    const float* W_ih0 = (const float*)d_in[1];
    const float* W_hh0 = (const float*)d_in[2];
    const float* b_ih0 = (const float*)d_in[3];
    const float* b_hh0 = (const float*)d_in[4];
    const float* W_ih1 = (const float*)d_in[5];
    const float* W_hh1 = (const float*)d_in[6];
    const float* b_ih1 = (const float*)d_in[7];
    const float* b_hh1 = (const float*)d_in[8];
    const float* W_out = (const float*)d_in[9];
    const float* b_out = (const float*)d_in[10];
    float* y = (float*)d_out;

    float *xg, *h0, *h1;
    unsigned* ctr;
    cudaGetSymbolAddress((void**)&xg, g_xg);
    cudaGetSymbolAddress((void**)&h0, g_h0);
    cudaGetSymbolAddress((void**)&h1, g_h1);
    cudaGetSymbolAddress((void**)&ctr, g_ctr);

    cudaFuncSetAttribute(gru_rec, cudaFuncAttributeMaxDynamicSharedMemorySize,
                         REC_SMEM_BYTES);

    cudaMemsetAsync(ctr, 0, 2 * sizeof(unsigned));

    const dim3 ggrid(NG_ / BN, (B_ * T_) / BM);   // 12 x 256

    // layer 0
    gemm_bias<<<ggrid, 256>>>(x, W_ih0, b_ih0, xg, B_ * T_, NG_, IN_);
    gru_rec<<<dim3(HID_ / RUT, B_ / RBT), 256, REC_SMEM_BYTES>>>(xg, W_hh0, b_hh0, h0, ctr);

    // layer 1
    gemm_bias<<<ggrid, 256>>>(h0, W_ih1, b_ih1, xg, B_ * T_, NG_, HID_);
    gru_rec<<<dim3(HID_ / RUT, B_ / RBT), 256, REC_SMEM_BYTES>>>(xg, W_hh1, b_hh1, h1, ctr + 1);

    // head
    out_proj<<<B_, 64>>>(h1, W_out, b_out, y);
}

// round 3
// speedup vs baseline: 1.9327x; 1.2207x over previous
#include <cuda_runtime.h>
#include <math.h>

#define B_    128
#define T_    256
#define IN_   256
#define HID_  512
#define NG_   1536   // 3*HID
#define OUT_  64

// ---------------- scratch (static __device__, no allocation) ----------------
__device__ float g_xg[(size_t)B_ * T_ * NG_];
__device__ float g_h0[(size_t)B_ * T_ * HID_];
__device__ float g_h1[(size_t)B_ * T_ * HID_];
__device__ unsigned g_ctr[2];

// ---------------- packed f32x2 helpers (Blackwell FFMA2) --------------------
__device__ __forceinline__ unsigned long long fma2(unsigned long long a,
                                                   unsigned long long b,
                                                   unsigned long long c) {
    unsigned long long d;
    asm("fma.rn.f32x2 %0, %1, %2, %3;" : "=l"(d) : "l"(a), "l"(b), "l"(c));
    return d;
}
__device__ __forceinline__ unsigned long long add2(unsigned long long a,
                                                   unsigned long long b) {
    unsigned long long d;
    asm("add.rn.f32x2 %0, %1, %2;" : "=l"(d) : "l"(a), "l"(b));
    return d;
}
__device__ __forceinline__ unsigned long long pack2(float x, float y) {
    unsigned long long r;
    asm("mov.b64 %0, {%1, %2};" : "=l"(r) : "f"(x), "f"(y));
    return r;
}
__device__ __forceinline__ void unpack2(unsigned long long v, float& x, float& y) {
    asm("mov.b64 {%0, %1}, %2;" : "=f"(x), "=f"(y) : "l"(v));
}

// ============================================================================
// GEMM: out[M,N] = X[M,K] @ W[N,K]^T + bias[N]   (both K-major)
// 128x128x8 tile, 256 threads, 8x8 micro-tile via f32x2 (n-pair packed accs).
// ============================================================================
#define BM 128
#define BN 128
#define BK 8

__global__ __launch_bounds__(256, 2)
void gemm_bias(const float* __restrict__ X, const float* __restrict__ W,
               const float* __restrict__ bias, float* __restrict__ out,
               int M, int N, int K)
{
    __shared__ float As[BK][BM + 4];
    __shared__ float Bs[BK][BN + 4];

    const int tid = threadIdx.x;
    const int tx  = tid & 15;
    const int ty  = tid >> 4;
    const int m0  = blockIdx.y * BM;
    const int n0  = blockIdx.x * BN;

    const int lr = tid >> 1;
    const int lc = (tid & 1) * 4;

    const float* Xp = X + (size_t)(m0 + lr) * K + lc;
    const float* Wp = W + (size_t)(n0 + lr) * K + lc;

    unsigned long long acc[8][4];
#pragma unroll
    for (int i = 0; i < 8; i++)
#pragma unroll
        for (int j = 0; j < 4; j++) acc[i][j] = 0ull;

    float4 pa = *(const float4*)Xp;
    float4 pb = *(const float4*)Wp;

    for (int k0 = 0; k0 < K; k0 += BK) {
        As[lc + 0][lr] = pa.x; As[lc + 1][lr] = pa.y;
        As[lc + 2][lr] = pa.z; As[lc + 3][lr] = pa.w;
        Bs[lc + 0][lr] = pb.x; Bs[lc + 1][lr] = pb.y;
        Bs[lc + 2][lr] = pb.z; Bs[lc + 3][lr] = pb.w;
        __syncthreads();

        if (k0 + BK < K) {
            pa = *(const float4*)(Xp + k0 + BK);
            pb = *(const float4*)(Wp + k0 + BK);
        }

#pragma unroll
        for (int kk = 0; kk < BK; kk++) {
            float4 a0 = *(const float4*)&As[kk][ty * 8];
            float4 a1 = *(const float4*)&As[kk][ty * 8 + 4];
            ulonglong2 b0 = *(const ulonglong2*)&Bs[kk][tx * 4];        // n pairs 0,1
            ulonglong2 b1 = *(const ulonglong2*)&Bs[kk][64 + tx * 4];   // n pairs 2,3
            float a[8] = {a0.x, a0.y, a0.z, a0.w, a1.x, a1.y, a1.z, a1.w};
#pragma unroll
            for (int i = 0; i < 8; i++) {
                unsigned long long a2 = pack2(a[i], a[i]);
                acc[i][0] = fma2(a2, b0.x, acc[i][0]);
                acc[i][1] = fma2(a2, b0.y, acc[i][1]);
                acc[i][2] = fma2(a2, b1.x, acc[i][2]);
                acc[i][3] = fma2(a2, b1.y, acc[i][3]);
            }
        }
        __syncthreads();
    }

    float4 bv0 = *(const float4*)(bias + n0 + tx * 4);
    float4 bv1 = *(const float4*)(bias + n0 + 64 + tx * 4);
#pragma unroll
    for (int i = 0; i < 8; i++) {
        int m = m0 + ty * 8 + i;
        float f0, f1, f2, f3;
        float4 o;
        unpack2(acc[i][0], f0, f1); unpack2(acc[i][1], f2, f3);
        o.x = f0 + bv0.x; o.y = f1 + bv0.y; o.z = f2 + bv0.z; o.w = f3 + bv0.w;
        *(float4*)(out + (size_t)m * N + n0 + tx * 4) = o;
        unpack2(acc[i][2], f0, f1); unpack2(acc[i][3], f2, f3);
        o.x = f0 + bv1.x; o.y = f1 + bv1.y; o.z = f2 + bv1.z; o.w = f3 + bv1.w;
        *(float4*)(out + (size_t)m * N + n0 + 64 + tx * 4) = o;
    }
}

// ============================================================================
// Persistent GRU recurrence. 128 CTAs = 32 unit-tiles (16 units) x 4 batch-tiles
// (32 rows). 256 threads = 2 k-split halves x 128. Thread: 4 batch x 1 unit x
// 3 gates = 12 packed-k f32x2 accumulators; 24 FMA2 per 7 LDS.128 per k4.
// ============================================================================
#define RBT 32               // batch rows per CTA
#define RUT 16               // hidden units per CTA
#define HP  516              // padded row stride (floats)
#define KSPLIT 256
#define REC_SMEM_BYTES ((RBT * HP + 48 * HP) * 4 + 128 * 12 * 8)

__global__ __launch_bounds__(256)
void gru_rec(const float* __restrict__ xg,   // [B*T, 1536]
             const float* __restrict__ Whh,  // [1536, 512]
             const float* __restrict__ bhh,  // [1536]
             float* __restrict__ hseq,       // [B, T, 512]
             unsigned* __restrict__ ctr)
{
    extern __shared__ float sm[];
    float* h_s = sm;                                    // [RBT][HP]
    float* W_s = sm + RBT * HP;                         // [48][HP], row = g*16+u
    unsigned long long* red =
        (unsigned long long*)(sm + RBT * HP + 48 * HP); // [128][12]
    __shared__ float bh_s[48];

    const int tid = threadIdx.x;
    const int u0  = blockIdx.x * RUT;
    const int b0  = blockIdx.y * RBT;
    const unsigned nCTA = gridDim.x * gridDim.y;

    // preload W_hh rows (48 x 512) and b_hh
    for (int i = tid; i < 48 * (HID_ / 4); i += 256) {
        int r  = i >> 7;             // 0..47
        int c4 = i & 127;
        int g = r >> 4, u = r & 15;
        float4 v = *(const float4*)(Whh + (size_t)(g * HID_ + u0 + u) * HID_ + c4 * 4);
        *(float4*)&W_s[r * HP + c4 * 4] = v;
    }
    if (tid < 48) {
        int g = tid >> 4, u = tid & 15;
        bh_s[tid] = bhh[g * HID_ + u0 + u];
    }

    const int ks = tid >> 7;         // k-split half
    const int r  = tid & 127;
    const int ug = r & 15;           // unit 0..15
    const int bg = r >> 4;           // batch group 0..7 -> rows bg+8i
    const int kb = ks * KSPLIT;

    const ulonglong2* wrp = (const ulonglong2*)(W_s + ( 0 + ug) * HP + kb);
    const ulonglong2* wzp = (const ulonglong2*)(W_s + (16 + ug) * HP + kb);
    const ulonglong2* wnp = (const ulonglong2*)(W_s + (32 + ug) * HP + kb);
    const ulonglong2* hAp = (const ulonglong2*)(h_s + (bg +  0) * HP + kb);
    const ulonglong2* hBp = (const ulonglong2*)(h_s + (bg +  8) * HP + kb);
    const ulonglong2* hCp = (const ulonglong2*)(h_s + (bg + 16) * HP + kb);
    const ulonglong2* hDp = (const ulonglong2*)(h_s + (bg + 24) * HP + kb);

    for (int t = 0; t < T_; t++) {
        // ---- stage previous h tile [32 x 512] into smem ----
        if (t == 0) {
            for (int i = tid; i < RBT * (HID_ / 4); i += 256)
                *(float4*)&h_s[(i >> 7) * HP + (i & 127) * 4] =
                    make_float4(0.f, 0.f, 0.f, 0.f);
        } else {
            for (int i = tid; i < RBT * (HID_ / 4); i += 256) {
                int rr = i >> 7, c4 = i & 127;
                const float* src = hseq + ((size_t)(b0 + rr) * T_ + (t - 1)) * HID_ + c4 * 4;
                unsigned sdst = (unsigned)__cvta_generic_to_shared(&h_s[rr * HP + c4 * 4]);
                asm volatile("cp.async.cg.shared.global [%0], [%1], 16;"
                             :: "r"(sdst), "l"(src));
            }
            asm volatile("cp.async.commit_group;");
            asm volatile("cp.async.wait_group 0;");
        }
        __syncthreads();

        // ---- prefetch xg[t] (ks0 threads only) ----
        float xr[4], xz[4], xn[4];
        if (ks == 0) {
#pragma unroll
            for (int i = 0; i < 4; i++) {
                size_t xb = ((size_t)(b0 + bg + 8 * i) * T_ + t) * NG_ + u0 + ug;
                xr[i] = __ldg(xg + xb);
                xz[i] = __ldg(xg + xb + 512);
                xn[i] = __ldg(xg + xb + 1024);
            }
        }

        unsigned long long ar0 = 0, ar1 = 0, ar2 = 0, ar3 = 0;
        unsigned long long az0 = 0, az1 = 0, az2 = 0, az3 = 0;
        unsigned long long an0 = 0, an1 = 0, an2 = 0, an3 = 0;

#pragma unroll 2
        for (int k4 = 0; k4 < KSPLIT / 4; k4++) {
            ulonglong2 w0 = wrp[k4];
            ulonglong2 w1 = wzp[k4];
            ulonglong2 w2 = wnp[k4];
            ulonglong2 hA = hAp[k4];
            ulonglong2 hB = hBp[k4];
            ulonglong2 hC = hCp[k4];
            ulonglong2 hD = hDp[k4];

            ar0 = fma2(hA.x, w0.x, ar0); ar0 = fma2(hA.y, w0.y, ar0);
            ar1 = fma2(hB.x, w0.x, ar1); ar1 = fma2(hB.y, w0.y, ar1);
            ar2 = fma2(hC.x, w0.x, ar2); ar2 = fma2(hC.y, w0.y, ar2);
            ar3 = fma2(hD.x, w0.x, ar3); ar3 = fma2(hD.y, w0.y, ar3);
            az0 = fma2(hA.x, w1.x, az0); az0 = fma2(hA.y, w1.y, az0);
            az1 = fma2(hB.x, w1.x, az1); az1 = fma2(hB.y, w1.y, az1);
            az2 = fma2(hC.x, w1.x, az2); az2 = fma2(hC.y, w1.y, az2);
            az3 = fma2(hD.x, w1.x, az3); az3 = fma2(hD.y, w1.y, az3);
            an0 = fma2(hA.x, w2.x, an0); an0 = fma2(hA.y, w2.y, an0);
            an1 = fma2(hB.x, w2.x, an1); an1 = fma2(hB.y, w2.y, an1);
            an2 = fma2(hC.x, w2.x, an2); an2 = fma2(hC.y, w2.y, an2);
            an3 = fma2(hD.x, w2.x, an3); an3 = fma2(hD.y, w2.y, an3);
        }

        // ---- cross-half reduction (packed) ----
        if (ks == 1) {
            unsigned long long* rp = red + r * 12;
            rp[0] = ar0; rp[1]  = ar1; rp[2]  = ar2; rp[3]  = ar3;
            rp[4] = az0; rp[5]  = az1; rp[6]  = az2; rp[7]  = az3;
            rp[8] = an0; rp[9]  = an1; rp[10] = an2; rp[11] = an3;
        }
        __syncthreads();

        if (ks == 0) {
            const unsigned long long* rp = red + r * 12;
            ar0 = add2(ar0, rp[0]); ar1 = add2(ar1, rp[1]);
            ar2 = add2(ar2, rp[2]); ar3 = add2(ar3, rp[3]);
            az0 = add2(az0, rp[4]); az1 = add2(az1, rp[5]);
            az2 = add2(az2, rp[6]); az3 = add2(az3, rp[7]);
            an0 = add2(an0, rp[8]); an1 = add2(an1, rp[9]);
            an2 = add2(an2, rp[10]); an3 = add2(an3, rp[11]);

            unsigned long long pr[4] = {ar0, ar1, ar2, ar3};
            unsigned long long pz[4] = {az0, az1, az2, az3};
            unsigned long long pn[4] = {an0, an1, an2, an3};
            const float br = bh_s[ug], bz = bh_s[16 + ug], bn = bh_s[32 + ug];
#pragma unroll
            for (int i = 0; i < 4; i++) {
                float lo, hi;
                unpack2(pr[i], lo, hi); float hr = lo + hi + br;
                unpack2(pz[i], lo, hi); float hz = lo + hi + bz;
                unpack2(pn[i], lo, hi); float hn = lo + hi + bn;
                float rr = 1.f / (1.f + __expf(-(xr[i] + hr)));
                float zz = 1.f / (1.f + __expf(-(xz[i] + hz)));
                float nn = tanhf(xn[i] + rr * hn);
                float hp = h_s[(bg + 8 * i) * HP + u0 + ug];
                int b = b0 + bg + 8 * i;
                hseq[((size_t)b * T_ + t) * HID_ + u0 + ug] =
                    (1.f - zz) * nn + zz * hp;
            }
        }
        __syncthreads();

        if (t < T_ - 1) {
            if (tid == 0) {
                __threadfence();
                atomicAdd(ctr, 1u);
                unsigned target = (unsigned)(t + 1) * nCTA;
                volatile unsigned* vc = ctr;
                while (*vc < target) { }
                __threadfence();
            }
            __syncthreads();
        }
    }
}

// ============================================================================
// Head
// ============================================================================
__global__ __launch_bounds__(64)
void out_proj(const float* __restrict__ hseq, const float* __restrict__ Wout,
              const float* __restrict__ bout, float* __restrict__ y)
{
    __shared__ float hs[HID_];
    const int b = blockIdx.x;
    const float* h = hseq + ((size_t)b * T_ + (T_ - 1)) * HID_;
    for (int i = threadIdx.x; i < HID_; i += 64) hs[i] = h[i];
    __syncthreads();

    const int o = threadIdx.x;
    float acc = bout[o];
    const float* w = Wout + (size_t)o * HID_;
#pragma unroll 4
    for (int k = 0; k < HID_; k += 4) {
        float4 wv = *(const float4*)(w + k);
        acc += hs[k] * wv.x + hs[k + 1] * wv.y + hs[k + 2] * wv.z + hs[k + 3] * wv.w;
    }
    y[b * OUT_ + o] = acc;
}

// ============================================================================
extern "C" void kernel_launch(void* const* d_in, const int* in_sizes, int n_in,
                              void* d_out, int out_size)
{
    (void)in_sizes; (void)n_in; (void)out_size;
    const float* x     = (const float*)d_in[0];
    const float* W_ih0 = (const float*)d_in[1];
    const float* W_hh0 = (const float*)d_in[2];
    const float* b_ih0 = (const float*)d_in[3];
    const float* b_hh0 = (const float*)d_in[4];
    const float* W_ih1 = (const float*)d_in[5];
    const float* W_hh1 = (const float*)d_in[6];
    const float* b_ih1 = (const float*)d_in[7];
    const float* b_hh1 = (const float*)d_in[8];
    const float* W_out = (const float*)d_in[9];
    const float* b_out = (const float*)d_in[10];
    float* y = (float*)d_out;

    float *xg, *h0, *h1;
    unsigned* ctr;
    cudaGetSymbolAddress((void**)&xg, g_xg);
    cudaGetSymbolAddress((void**)&h0, g_h0);
    cudaGetSymbolAddress((void**)&h1, g_h1);
    cudaGetSymbolAddress((void**)&ctr, g_ctr);

    cudaFuncSetAttribute(gru_rec, cudaFuncAttributeMaxDynamicSharedMemorySize,
                         REC_SMEM_BYTES);

    cudaMemsetAsync(ctr, 0, 2 * sizeof(unsigned));

    const dim3 ggrid(NG_ / BN, (B_ * T_) / BM);   // 12 x 256

    gemm_bias<<<ggrid, 256>>>(x, W_ih0, b_ih0, xg, B_ * T_, NG_, IN_);
    gru_rec<<<dim3(HID_ / RUT, B_ / RBT), 256, REC_SMEM_BYTES>>>(xg, W_hh0, b_hh0, h0, ctr);

    gemm_bias<<<ggrid, 256>>>(h0, W_ih1, b_ih1, xg, B_ * T_, NG_, HID_);
    gru_rec<<<dim3(HID_ / RUT, B_ / RBT), 256, REC_SMEM_BYTES>>>(xg, W_hh1, b_hh1, h1, ctr + 1);

    out_proj<<<B_, 64>>>(h1, W_out, b_out, y);
}